// round 7
// baseline (speedup 1.0000x reference)
#include <cuda_runtime.h>
#include <cstdint>
#include <cstddef>

// Problem constants
#define T_STEPS 2048
#define BATCH   256
#define FEAT    64
#define HID     256
#define KDIM    320
#define THREADS 512

// RNN smem: 96KB weights + h double-buffer
// per-thread smem weights: 12 chunks (jj2 upper half + jj3), [warp][chunk][lane] float4
#define WSM_WORDS (16 * 12 * 32 * 4)     // 24576 words = 96KB
#define SLICEW 36                         // 32 h + 4 pad (distinct 16B groups per slice)
#define BROWW  292                        // 8*36 + 4
#define BUFW   (2 * BROWW)                // 584 words (2 batches)
#define COMB_WORDS (2 * BUFW)             // 1168
#define SMEM_BYTES ((WSM_WORDS + COMB_WORDS) * 4)   // 102,976 B

// Precomputed U[t][b][j] = b0[j] + sum_{k<64} x[t,b,k] * W0[j,k]  (512MB scratch)
__device__ float g_U[(size_t)T_STEPS * BATCH * HID];

__device__ __forceinline__ float lo32(unsigned long long v) {
    return __uint_as_float((unsigned)(v & 0xffffffffull));
}
__device__ __forceinline__ float hi32(unsigned long long v) {
    return __uint_as_float((unsigned)(v >> 32));
}
__device__ __forceinline__ unsigned long long pk2(float a, float b) {
    return (unsigned long long)__float_as_uint(a) |
           ((unsigned long long)__float_as_uint(b) << 32);
}
__device__ __forceinline__ void fma2(unsigned long long& acc,
                                     unsigned long long w, unsigned long long c) {
    asm("fma.rn.f32x2 %0, %1, %2, %0;" : "+l"(acc) : "l"(w), "l"(c));
}
__device__ __forceinline__ void redg_add(float* p, float v) {
    asm volatile("red.global.add.f32 [%0], %1;" :: "l"(p), "f"(v) : "memory");
}

// ---- init kernel: out[b][t] = bfc ----
__global__ void init_out_kernel(const float* __restrict__ bfc,
                                float* __restrict__ out) {
    int i = blockIdx.x * blockDim.x + threadIdx.x;
    out[i] = bfc[0];
}

// ---- precompute U: one CTA per t, 512 threads = 2 b-halves x 256 j ----
__global__ void __launch_bounds__(512)
precompute_u_kernel(const float* __restrict__ x,   // (T, B, F)
                    const float* __restrict__ W0,  // (H, 320)
                    const float* __restrict__ b0)  // (H)
{
    extern __shared__ float xs[];                  // 256 b x 64 k = 64KB
    const int t   = blockIdx.x;
    const int tid = threadIdx.x;
    const int j   = tid & 255;
    const int bh  = tid >> 8;                      // 0/1 -> b in [bh*128, bh*128+128)

    // weights W0[j][0..63] packed as 32 f32x2
    unsigned long long w[32];
    {
        const float4* wp = reinterpret_cast<const float4*>(W0 + (size_t)j * KDIM);
        #pragma unroll
        for (int q = 0; q < 16; ++q) {
            float4 v = wp[q];
            w[2 * q]     = pk2(v.x, v.y);
            w[2 * q + 1] = pk2(v.z, v.w);
        }
    }
    const float b0j = b0[j];

    // stage x[t] tile (coalesced float4)
    {
        const float4* xg = reinterpret_cast<const float4*>(x + (size_t)t * BATCH * FEAT);
        float4* xs4 = reinterpret_cast<float4*>(xs);
        #pragma unroll
        for (int i = tid; i < BATCH * FEAT / 4; i += 512) xs4[i] = xg[i];
    }
    __syncthreads();

    float* Ut = g_U + (size_t)t * BATCH * HID;
    for (int b = bh * 128; b < bh * 128 + 128; ++b) {
        const ulonglong2* xr = reinterpret_cast<const ulonglong2*>(xs + b * FEAT);
        unsigned long long acc = 0ull;
        #pragma unroll
        for (int c = 0; c < 16; ++c) {
            ulonglong2 xv = xr[c];
            fma2(acc, w[2 * c],     xv.x);
            fma2(acc, w[2 * c + 1], xv.y);
        }
        Ut[b * HID + j] = lo32(acc) + hi32(acc) + b0j;   // coalesced over j
    }
}

// ---- serial RNN loop: K = 256 (h only), U added per step ----
__global__ void __launch_bounds__(THREADS, 1)
rnn_seq_kernel(const float* __restrict__ W0,   // (H, 320) — h-part cols 64..319
               const float* __restrict__ Wfc,  // (1, H)
               float* __restrict__ out)        // (B, T)
{
    extern __shared__ float smem[];
    float* const wsm  = smem;
    float* const comb = smem + WSM_WORDS;

    const int tid  = threadIdx.x;
    const int w    = tid >> 5;            // warp 0..15
    const int lane = tid & 31;
    const int s    = lane & 7;            // k-slice 0..7 (32 h each)
    const int jg   = tid >> 3;            // j-group 0..63 (4 j each)
    const int bg   = blockIdx.x * 2;      // first batch of this CTA
    const int j0   = jg * 4;

    // ---- RF weights: jj0, jj1 full (16 kpairs each) + jj2 first half (8 kpairs) ----
    unsigned long long wr[32], wr2[8];
    #pragma unroll
    for (int jj = 0; jj < 2; ++jj) {
        const float4* wp = reinterpret_cast<const float4*>(
            W0 + (size_t)(j0 + jj) * KDIM + FEAT + s * 32);
        #pragma unroll
        for (int q = 0; q < 8; ++q) {
            float4 v = wp[q];
            wr[jj * 16 + 2 * q]     = pk2(v.x, v.y);
            wr[jj * 16 + 2 * q + 1] = pk2(v.z, v.w);
        }
    }
    {
        const float4* wp = reinterpret_cast<const float4*>(
            W0 + (size_t)(j0 + 2) * KDIM + FEAT + s * 32);
        #pragma unroll
        for (int q = 0; q < 4; ++q) {
            float4 v = wp[q];
            wr2[2 * q]     = pk2(v.x, v.y);
            wr2[2 * q + 1] = pk2(v.z, v.w);
        }
    }
    // ---- smem weights: chunk i<4 -> jj2 chunks 4..7; i>=4 -> jj3 chunks 0..7 ----
    #pragma unroll
    for (int i = 0; i < 12; ++i) {
        int jj = (i < 4) ? 2 : 3;
        int ci = (i < 4) ? (4 + i) : (i - 4);
        float4 v = *reinterpret_cast<const float4*>(
            W0 + (size_t)(j0 + jj) * KDIM + FEAT + s * 32 + ci * 4);
        *reinterpret_cast<float4*>(wsm + w * 1536 + i * 128 + lane * 4) = v;
    }

    // After butterfly: lane owns (jm = j0 + (s>>1), bm = s&1)
    const int jm = j0 + (s >> 1);
    const int bm = s & 1;
    const float wfcj = Wfc[jm];
    const int hword  = bm * BROWW + (jm >> 5) * SLICEW + (jm & 31);

    // zero both h buffers (h0 = 0)
    for (int i = tid; i < COMB_WORDS; i += THREADS) comb[i] = 0.f;
    __syncthreads();

    const ulonglong2* const WS =
        reinterpret_cast<const ulonglong2*>(wsm) + (size_t)w * 384 + lane;
    float* const outp = out + (size_t)(bg + bm) * T_STEPS;
    const float* const Up = g_U + (size_t)(bg + bm) * HID + jm;

    float uval = Up[0];                   // U[t=0]
    int cur = 0;

    for (int t = 0; t < T_STEPS; ++t) {
        // prefetch next U (consumed at end of next iteration)
        float un = 0.f;
        if (t + 1 < T_STEPS) un = Up[(size_t)(t + 1) * BATCH * HID];

        // ---- dot products over this slice's 32 h: 8 chunks x 4 j x 2 b ----
        unsigned long long acc[8];
        #pragma unroll
        for (int i = 0; i < 8; ++i) acc[i] = 0ull;

        const ulonglong2* A0 = reinterpret_cast<const ulonglong2*>(comb)
                               + cur * 146 + s * 9;
        const ulonglong2* A1 = A0 + 73;

        #pragma unroll
        for (int c = 0; c < 8; ++c) {
            ulonglong2 a0 = A0[c];
            ulonglong2 a1 = A1[c];
            fma2(acc[0], wr[2 * c],          a0.x); fma2(acc[0], wr[2 * c + 1],      a0.y);
            fma2(acc[1], wr[2 * c],          a1.x); fma2(acc[1], wr[2 * c + 1],      a1.y);
            fma2(acc[2], wr[16 + 2 * c],     a0.x); fma2(acc[2], wr[16 + 2 * c + 1], a0.y);
            fma2(acc[3], wr[16 + 2 * c],     a1.x); fma2(acc[3], wr[16 + 2 * c + 1], a1.y);
            if (c < 4) {
                fma2(acc[4], wr2[2 * c],     a0.x); fma2(acc[4], wr2[2 * c + 1],     a0.y);
                fma2(acc[5], wr2[2 * c],     a1.x); fma2(acc[5], wr2[2 * c + 1],     a1.y);
            } else {
                ulonglong2 wv = WS[(c - 4) * 32];
                fma2(acc[4], wv.x, a0.x);           fma2(acc[4], wv.y, a0.y);
                fma2(acc[5], wv.x, a1.x);           fma2(acc[5], wv.y, a1.y);
            }
            ulonglong2 w3 = WS[(4 + c) * 32];
            fma2(acc[6], w3.x, a0.x);               fma2(acc[6], w3.y, a0.y);
            fma2(acc[7], w3.x, a1.x);               fma2(acc[7], w3.y, a1.y);
        }

        // fold k-pairs: v[m], m = jj*2 + b
        float v[8];
        #pragma unroll
        for (int i = 0; i < 8; ++i) v[i] = lo32(acc[i]) + hi32(acc[i]);

        // ---- value-halving butterfly over the 8 slice lanes ----
        #pragma unroll
        for (int k = 0; k < 4; ++k) {
            float t1 = __shfl_xor_sync(0xffffffffu, v[k],     4);
            float t2 = __shfl_xor_sync(0xffffffffu, v[4 + k], 4);
            v[k] = (s & 4) ? (v[4 + k] + t2) : (v[k] + t1);
        }
        #pragma unroll
        for (int k = 0; k < 2; ++k) {
            float t1 = __shfl_xor_sync(0xffffffffu, v[k],     2);
            float t2 = __shfl_xor_sync(0xffffffffu, v[2 + k], 2);
            v[k] = (s & 2) ? (v[2 + k] + t2) : (v[k] + t1);
        }
        {
            float t1 = __shfl_xor_sync(0xffffffffu, v[0], 1);
            float t2 = __shfl_xor_sync(0xffffffffu, v[1], 1);
            v[0] = (s & 1) ? (v[1] + t2) : (v[0] + t1);
        }

        // pre-activation = h-dot + U (bias folded into U); accurate tanh
        float pre = v[0] + uval;
        pre = fminf(fmaxf(pre, -15.f), 15.f);
        float e = __expf(2.f * pre);
        float h = 1.f - __fdividef(2.f, e + 1.f);

        // write h into NEXT buffer
        const int nxt = cur ^ 1;
        comb[nxt * BUFW + hword] = h;

        __syncthreads();   // single barrier per step

        // post-barrier: fire-and-forget output partial (L2 serializes per addr)
        redg_add(outp + t, h * wfcj);

        uval = un;
        cur = nxt;
    }
}

extern "C" void kernel_launch(void* const* d_in, const int* in_sizes, int n_in,
                              void* d_out, int out_size) {
    const float* x   = (const float*)d_in[0];
    const float* W0  = (const float*)d_in[1];
    const float* b0  = (const float*)d_in[2];
    const float* Wfc = (const float*)d_in[3];
    const float* bfc = (const float*)d_in[4];
    float* out = (float*)d_out;
    (void)in_sizes; (void)n_in; (void)out_size;

    // 1) out[b][t] = bfc
    init_out_kernel<<<(BATCH * T_STEPS) / 256, 256>>>(bfc, out);

    // 2) precompute U = b0 + x*W0x^T  (parallel over t; FMA-bound ~240us)
    cudaFuncSetAttribute(precompute_u_kernel,
                         cudaFuncAttributeMaxDynamicSharedMemorySize, 65536);
    precompute_u_kernel<<<T_STEPS, 512, 65536>>>(x, W0, b0);

    // 3) serial RNN loop on K=256 only
    cudaFuncSetAttribute(rnn_seq_kernel,
                         cudaFuncAttributeMaxDynamicSharedMemorySize, SMEM_BYTES);
    rnn_seq_kernel<<<BATCH / 2, THREADS, SMEM_BYTES>>>(W0, Wfc, out);
}

// round 9
// speedup vs baseline: 1.0356x; 1.0356x over previous
#include <cuda_runtime.h>
#include <cstdint>
#include <cstddef>

// Problem constants
#define T_STEPS 2048
#define BATCH   256
#define FEAT    64
#define KDIM    320            // FEAT + HID
#define THREADS 512
#define NWARP   16

// SMEM layout (dynamic):
//  [0, WSM_WORDS)        : smem-resident weight half (jj=2,3), 160KB
//  [WSM_WORDS, +2*BUFW)  : comb double buffer
#define WSM_WORDS (NWARP * 20 * 128)     // 16 warps * 20 chunks * 512B = 160KB
#define SLICEW 44                         // 40 data + 4 pad (distinct 16B groups)
#define BROWW  356                        // 8*44 + 4
#define BUFW   (2 * BROWW)                // 712 words (2 batches)
#define COMB_WORDS (2 * BUFW)             // 1424
#define SMEM_BYTES ((WSM_WORDS + COMB_WORDS) * 4)   // 169,536 B

__device__ __forceinline__ float lo32(unsigned long long v) {
    return __uint_as_float((unsigned)(v & 0xffffffffull));
}
__device__ __forceinline__ float hi32(unsigned long long v) {
    return __uint_as_float((unsigned)(v >> 32));
}
__device__ __forceinline__ unsigned long long pk2(float a, float b) {
    return (unsigned long long)__float_as_uint(a) |
           ((unsigned long long)__float_as_uint(b) << 32);
}
__device__ __forceinline__ void fma2(unsigned long long& acc,
                                     unsigned long long w, unsigned long long c) {
    asm("fma.rn.f32x2 %0, %1, %2, %0;" : "+l"(acc) : "l"(w), "l"(c));
}
__device__ __forceinline__ void redg_add(float* p, float v) {
    asm volatile("red.global.add.f32 [%0], %1;" :: "l"(p), "f"(v) : "memory");
}

// word index within one comb buffer for (b, k)
__device__ __forceinline__ int cword(int b, int k) {
    return b * BROWW + (k / 40) * SLICEW + (k % 40);
}

// ---- init kernel: out[b][t] = bfc (REDG partials accumulate on top) ----
__global__ void init_out_kernel(const float* __restrict__ bfc,
                                float* __restrict__ out) {
    int i = blockIdx.x * blockDim.x + threadIdx.x;
    out[i] = bfc[0];
}

__global__ void __launch_bounds__(THREADS, 1)
rnn_seq_kernel(const float* __restrict__ x,    // (T, B, F)
               const float* __restrict__ W0,   // (H, F+H)
               const float* __restrict__ b0,   // (H)
               const float* __restrict__ Wfc,  // (1, H)
               float* __restrict__ out)        // (B, T)
{
    extern __shared__ float smem[];
    float* const wsm  = smem;
    float* const comb = smem + WSM_WORDS;

    const int tid  = threadIdx.x;
    const int w    = tid >> 5;            // warp 0..15
    const int lane = tid & 31;
    const int s    = lane & 7;            // k-slice 0..7 (40 k each)
    const int jg   = tid >> 3;            // j-group 0..63 (4 j each)
    const int bg   = blockIdx.x * 2;      // first batch of this CTA

    // ---- RF weights: jj = 0,1 -> W0[jg*4+jj][40s..40s+40) as 20 f32x2 each ----
    unsigned long long wr[40];
    #pragma unroll
    for (int jj = 0; jj < 2; ++jj) {
        const float4* wp = reinterpret_cast<const float4*>(
            W0 + (size_t)(jg * 4 + jj) * KDIM + s * 40);
        #pragma unroll
        for (int q = 0; q < 10; ++q) {
            float4 v = wp[q];
            wr[jj * 20 + 2 * q]     = pk2(v.x, v.y);
            wr[jj * 20 + 2 * q + 1] = pk2(v.z, v.w);
        }
    }
    // ---- SMEM weights: jj = 2,3. Layout: [warp][chunk 0..19][lane] float4 ----
    {
        float4* dst = reinterpret_cast<float4*>(wsm) + (size_t)w * 640 + lane;
        #pragma unroll
        for (int jj = 0; jj < 2; ++jj) {
            const float4* wp = reinterpret_cast<const float4*>(
                W0 + (size_t)(jg * 4 + 2 + jj) * KDIM + s * 40);
            #pragma unroll
            for (int q = 0; q < 10; ++q)
                dst[(jj * 10 + q) * 32] = wp[q];
        }
    }

    // After butterfly: lane owns (j = jg*4 + (s>>1), b = s&1)
    const int jm = jg * 4 + (s >> 1);
    const int bm = s & 1;
    const float b0j  = b0[jm];
    const float wfcj = Wfc[jm];
    const int hword  = cword(bm, FEAT + jm);

    // x deposit: threads 0..127 each own one (b, f)
    const bool xown = tid < 2 * FEAT;
    const int xb = (tid >> 6) & 1;
    const int xf = tid & 63;
    const int xword = cword(xb, xf);

    // zero both comb buffers (h region of buf0 must be 0 at t=0)
    for (int i = tid; i < COMB_WORDS; i += THREADS) comb[i] = 0.f;
    __syncthreads();

    float xval = 0.f;
    const float* xp = x + ((size_t)2 * BATCH + bg + xb) * FEAT + xf;   // -> x_2
    if (xown) {
        comb[xword] = x[((size_t)0 * BATCH + bg + xb) * FEAT + xf];    // x_0
        xval        = x[((size_t)1 * BATCH + bg + xb) * FEAT + xf];    // x_1
    }
    __syncthreads();

    const ulonglong2* const WS =
        reinterpret_cast<const ulonglong2*>(wsm) + (size_t)w * 640 + lane;

    int cur = 0;

    for (int t = 0; t < T_STEPS; ++t) {
        // ---- dot products: 10 float4-chunks x 4 j x 2 b ----
        unsigned long long acc[8];
        #pragma unroll
        for (int i = 0; i < 8; ++i) acc[i] = 0ull;

        const ulonglong2* A0 = reinterpret_cast<const ulonglong2*>(
            comb + cur * BUFW + s * SLICEW);
        const ulonglong2* A1 = reinterpret_cast<const ulonglong2*>(
            comb + cur * BUFW + BROWW + s * SLICEW);

        #pragma unroll
        for (int q = 0; q < 10; ++q) {
            ulonglong2 a0 = A0[q];             // acts kpairs (2q,2q+1), batch 0
            ulonglong2 a1 = A1[q];             // batch 1
            ulonglong2 wc = WS[q * 32];        // weights jj=2
            ulonglong2 wd = WS[(10 + q) * 32]; // weights jj=3
            fma2(acc[0], wr[2 * q],      a0.x); fma2(acc[0], wr[2 * q + 1],      a0.y);
            fma2(acc[1], wr[2 * q],      a1.x); fma2(acc[1], wr[2 * q + 1],      a1.y);
            fma2(acc[2], wr[20 + 2 * q], a0.x); fma2(acc[2], wr[20 + 2 * q + 1], a0.y);
            fma2(acc[3], wr[20 + 2 * q], a1.x); fma2(acc[3], wr[20 + 2 * q + 1], a1.y);
            fma2(acc[4], wc.x, a0.x);           fma2(acc[4], wc.y, a0.y);
            fma2(acc[5], wc.x, a1.x);           fma2(acc[5], wc.y, a1.y);
            fma2(acc[6], wd.x, a0.x);           fma2(acc[6], wd.y, a0.y);
            fma2(acc[7], wd.x, a1.x);           fma2(acc[7], wd.y, a1.y);
        }

        // fold k-pairs to scalars: v[m], m = jj*2 + b
        float v[8];
        #pragma unroll
        for (int i = 0; i < 8; ++i) v[i] = lo32(acc[i]) + hi32(acc[i]);

        // ---- value-halving butterfly over the 8 slice lanes ----
        #pragma unroll
        for (int k = 0; k < 4; ++k) {
            float t1 = __shfl_xor_sync(0xffffffffu, v[k],     4);
            float t2 = __shfl_xor_sync(0xffffffffu, v[4 + k], 4);
            v[k] = (s & 4) ? (v[4 + k] + t2) : (v[k] + t1);
        }
        #pragma unroll
        for (int k = 0; k < 2; ++k) {
            float t1 = __shfl_xor_sync(0xffffffffu, v[k],     2);
            float t2 = __shfl_xor_sync(0xffffffffu, v[2 + k], 2);
            v[k] = (s & 2) ? (v[2 + k] + t2) : (v[k] + t1);
        }
        {
            float t1 = __shfl_xor_sync(0xffffffffu, v[0], 1);
            float t2 = __shfl_xor_sync(0xffffffffu, v[1], 1);
            v[0] = (s & 1) ? (v[1] + t2) : (v[0] + t1);
        }

        // lane owns (jm, bm): accurate tanh via exp identity (inf-safe, no clamp)
        float pre = v[0] + b0j;
        float e = __expf(2.f * pre);
        float h = 1.f - __fdividef(2.f, e + 1.f);

        // write h + x_{t+1} into NEXT buffer (local smem only)
        const int nxt = cur ^ 1;
        comb[nxt * BUFW + hword] = h;
        if (xown) comb[nxt * BUFW + xword] = xval;

        // split barrier: release stores, overlap the tail with barrier latency
        asm volatile("bar.arrive 0, 1024;" ::: "memory");

        // ---- shadow region ----
        if (xown && (t + 2) < T_STEPS) { xval = *xp; xp += (size_t)BATCH * FEAT; }

        // output partials: sum h*Wfc over j within warp (preserves lane bit0 = bm)
        float po = h * wfcj;
        po += __shfl_xor_sync(0xffffffffu, po, 2);
        po += __shfl_xor_sync(0xffffffffu, po, 4);
        po += __shfl_xor_sync(0xffffffffu, po, 8);
        po += __shfl_xor_sync(0xffffffffu, po, 16);
        if (lane < 2)
            redg_add(out + (size_t)(bg + lane) * T_STEPS + t, po);

        asm volatile("bar.sync 0, 1024;" ::: "memory");

        cur = nxt;
    }
}

extern "C" void kernel_launch(void* const* d_in, const int* in_sizes, int n_in,
                              void* d_out, int out_size) {
    const float* x   = (const float*)d_in[0];
    const float* W0  = (const float*)d_in[1];
    const float* b0  = (const float*)d_in[2];
    const float* Wfc = (const float*)d_in[3];
    const float* bfc = (const float*)d_in[4];
    float* out = (float*)d_out;
    (void)in_sizes; (void)n_in; (void)out_size;

    // 1) out[b][t] = bfc  (256*2048 elements)
    init_out_kernel<<<(BATCH * T_STEPS) / 256, 256>>>(bfc, out);

    // 2) single-CTA-per-batch-pair RNN: 128 CTAs, 512 threads, 169.5KB dyn smem
    cudaFuncSetAttribute(rnn_seq_kernel,
                         cudaFuncAttributeMaxDynamicSharedMemorySize, SMEM_BYTES);
    rnn_seq_kernel<<<BATCH / 2, THREADS, SMEM_BYTES>>>(x, W0, b0, Wfc, out);
}